// round 6
// baseline (speedup 1.0000x reference)
#include <cuda_runtime.h>
#include <cstdint>

#define Bz 32
#define Hh 512
#define Ll 2
#define Tt 20
#define Vv 10000
#define Ss 49

typedef unsigned long long ull;

// ---------------- device state (no allocations allowed) ----------------
__device__ __align__(16) float g_embT[Hh * Bz];          // k4b4 layout
__device__ __align__(16) float g_hA[Ll][Hh * Bz];        // gated h (LSTM input), k4b4
__device__ __align__(16) float g_hB[Ll][Hh * Bz];        // post-LSTM h, k4b4
__device__ __align__(16) float g_cT[Ll][Hh * Bz];        // plain [k*32+b]
__device__ __align__(16) float g_attnT[Ll][Hh * Bz];     // k4b4
__device__ float g_q[Ll][Hh][Bz];
__device__ float g_keysT[Bz * Ss * Hh];                  // [b][s][d]
__device__ float g_vals[Bz * Hh * Ss];                   // [b][d][s]
__device__ ull   g_amax[Bz];

// ---------------- helpers ----------------
__device__ __forceinline__ void fma2(ull& d, ull a, ull b) {
    asm("fma.rn.f32x2 %0, %1, %2, %0;" : "+l"(d) : "l"(a), "l"(b));
}
__device__ __forceinline__ float unpk_sum(ull v) {
    float lo, hi;
    asm("mov.b64 {%0,%1}, %2;" : "=f"(lo), "=f"(hi) : "l"(v));
    return lo + hi;
}
__device__ __forceinline__ int K4B(int k, int b) { return ((k >> 2) * Bz + b) * 4 + (k & 3); }
__device__ __forceinline__ float sigf(float x) { return 1.0f / (1.0f + expf(-x)); }
__device__ __forceinline__ unsigned fkey(float f) {
    unsigned u = __float_as_uint(f);
    return (u & 0x80000000u) ? ~u : (u | 0x80000000u);
}

// ---------------- init ----------------
__global__ void k_init(const float* __restrict__ pooled, const float* __restrict__ embed,
                       const int* __restrict__ sosp) {
    int i = blockIdx.x * blockDim.x + threadIdx.x;   // 32768 threads
    int sos = sosp[0];
    if (i < Ll * Hh * Bz) {
        int l = i / (Hh * Bz);
        int r = i % (Hh * Bz);
        int k = r >> 5, b = r & 31;
        float pv = pooled[b * Hh + k];
        g_hA[l][K4B(k, b)] = pv;
        g_cT[l][k * Bz + b] = pv;
    }
    if (i < Hh * Bz) {
        int k = i >> 5, b = i & 31;
        g_embT[K4B(k, b)] = embed[sos * Hh + k];
    }
    if (i < Bz) g_amax[i] = 0ull;
}

// ---------------- keys/values precompute (once) ----------------
__global__ void k_kv(const float* __restrict__ img, const float* __restrict__ Wk,
                     const float* __restrict__ bk, const float* __restrict__ Wv,
                     const float* __restrict__ bv) {
    int bd = blockIdx.x;               // b*512 + d
    int b = bd >> 9, d = bd & 511;
    __shared__ float ch[Ss];
    int tid = threadIdx.x;
    if (tid < Ss) ch[tid] = img[(b * Hh + d) * Ss + tid];
    __syncthreads();
    if (tid < Ss) {
        int s = tid;
        float ka = bk[s], va = bv[s];
        const float* wkr = Wk + s * Ss;
        const float* wvr = Wv + s * Ss;
#pragma unroll
        for (int s2 = 0; s2 < Ss; s2++) {
            float c = ch[s2];
            ka = fmaf(c, wkr[s2], ka);
            va = fmaf(c, wvr[s2], va);
        }
        g_keysT[(b * Ss + s) * Hh + d] = tanhf(ka);
        g_vals[(b * Hh + d) * Ss + s] = tanhf(va);
    }
}

// ---------------- LSTM layer (one warp per gate-quadruple jj, lanes = batch) ----------------
__global__ __launch_bounds__(128) void k_lstm(
    int layer, int x_is_emb,
    const longlong2* __restrict__ Wih, const longlong2* __restrict__ Whh,
    const float* __restrict__ bih, const float* __restrict__ bhh) {
    int jj = (blockIdx.x * blockDim.x + threadIdx.x) >> 5;  // 0..511
    int b = threadIdx.x & 31;
    const longlong2* xT = x_is_emb ? (const longlong2*)g_embT : (const longlong2*)g_hB[0];
    const longlong2* hT = (const longlong2*)g_hA[layer];
    float* cT = g_cT[layer];
    float* hOut = g_hB[layer];

    ull acc[4] = {0ull, 0ull, 0ull, 0ull};
    for (int k4 = 0; k4 < Hh / 4; k4++) {
        longlong2 xv = xT[k4 * Bz + b];
        longlong2 hv = hT[k4 * Bz + b];
#pragma unroll
        for (int g = 0; g < 4; g++) {
            int r = g * Hh + jj;
            longlong2 wi = Wih[r * (Hh / 4) + k4];
            longlong2 wh = Whh[r * (Hh / 4) + k4];
            fma2(acc[g], (ull)wi.x, (ull)xv.x);
            fma2(acc[g], (ull)wi.y, (ull)xv.y);
            fma2(acc[g], (ull)wh.x, (ull)hv.x);
            fma2(acc[g], (ull)wh.y, (ull)hv.y);
        }
    }
    float gate[4];
#pragma unroll
    for (int g = 0; g < 4; g++)
        gate[g] = unpk_sum(acc[g]) + bih[g * Hh + jj] + bhh[g * Hh + jj];
    float iv = sigf(gate[0]), fv = sigf(gate[1]);
    float gv = tanhf(gate[2]), ov = sigf(gate[3]);
    int ci = jj * Bz + b;
    float c2 = fv * cT[ci] + iv * gv;
    cT[ci] = c2;
    hOut[K4B(jj, b)] = ov * tanhf(c2);
}

// ---------------- projection: logits -> res column + argmax ----------------
__global__ __launch_bounds__(128) void k_proj(
    int src_is_emb, const longlong2* __restrict__ W, const float* __restrict__ pb,
    float* __restrict__ res, int t, int do_amax) {
    __shared__ ull samax[Bz];
    int tid = threadIdx.x;
    if (tid < Bz) samax[tid] = 0ull;
    __syncthreads();
    const longlong2* xT = src_is_emb ? (const longlong2*)g_embT : (const longlong2*)g_hB[1];
    int warp = (blockIdx.x * blockDim.x + tid) >> 5;   // 0..2499
    int b = tid & 31;
    int v0 = warp * 4;
    ull acc[4] = {0ull, 0ull, 0ull, 0ull};
    for (int k4 = 0; k4 < Hh / 4; k4++) {
        longlong2 xv = xT[k4 * Bz + b];
#pragma unroll
        for (int r = 0; r < 4; r++) {
            longlong2 w = W[(v0 + r) * (Hh / 4) + k4];
            fma2(acc[r], (ull)w.x, (ull)xv.x);
            fma2(acc[r], (ull)w.y, (ull)xv.y);
        }
    }
    ull best = 0ull;
#pragma unroll
    for (int r = 0; r < 4; r++) {
        int v = v0 + r;
        float lg = unpk_sum(acc[r]) + pb[v];
        res[b * (Vv * Tt) + v * Tt + t] = lg;
        ull pk = ((ull)fkey(lg) << 32) | (unsigned)(~(unsigned)v);
        if (pk > best) best = pk;
    }
    if (do_amax) {
        atomicMax(&samax[b], best);
        __syncthreads();
        if (tid < Bz) atomicMax(&g_amax[tid], samax[tid]);
    }
}

// ---------------- q = tanh(h @ Wq^T + bq), both layers share weight loads ----------------
__global__ __launch_bounds__(128) void k_q(const longlong2* __restrict__ Wq,
                                           const float* __restrict__ bq) {
    int warp = (blockIdx.x * blockDim.x + threadIdx.x) >> 5;  // 0..127
    int b = threadIdx.x & 31;
    int d0 = warp * 4;
    const longlong2* h0 = (const longlong2*)g_hB[0];
    const longlong2* h1 = (const longlong2*)g_hB[1];
    ull a0[4] = {0ull, 0ull, 0ull, 0ull}, a1[4] = {0ull, 0ull, 0ull, 0ull};
    for (int k4 = 0; k4 < Hh / 4; k4++) {
        longlong2 x0 = h0[k4 * Bz + b];
        longlong2 x1 = h1[k4 * Bz + b];
#pragma unroll
        for (int r = 0; r < 4; r++) {
            longlong2 w = Wq[(d0 + r) * (Hh / 4) + k4];
            fma2(a0[r], (ull)w.x, (ull)x0.x);
            fma2(a0[r], (ull)w.y, (ull)x0.y);
            fma2(a1[r], (ull)w.x, (ull)x1.x);
            fma2(a1[r], (ull)w.y, (ull)x1.y);
        }
    }
#pragma unroll
    for (int r = 0; r < 4; r++) {
        int d = d0 + r;
        g_q[0][d][b] = tanhf(unpk_sum(a0[r]) + bq[d]);
        g_q[1][d][b] = tanhf(unpk_sum(a1[r]) + bq[d]);
    }
}

// ---------------- attention (scores/softmax/attn) + greedy-token embedding gather ----------------
__global__ __launch_bounds__(256) void k_att(const float* __restrict__ embed) {
    int l = blockIdx.x >> 5, b = blockIdx.x & 31;
    int tid = threadIdx.x;
    __shared__ float sq[Hh];
    __shared__ float sw[64];
    for (int d = tid; d < Hh; d += 256) sq[d] = g_q[l][d][b];
    __syncthreads();
    int w = tid >> 5, lane = tid & 31;
    for (int s = w; s < Ss; s += 8) {
        const float* kr = g_keysT + (b * Ss + s) * Hh;
        float acc = 0.f;
        for (int d = lane; d < Hh; d += 32) acc = fmaf(sq[d], kr[d], acc);
#pragma unroll
        for (int o = 16; o > 0; o >>= 1) acc += __shfl_down_sync(0xffffffffu, acc, o);
        if (lane == 0) sw[s] = acc * (1.0f / 7.0f);
    }
    __syncthreads();
    if (w == 0) {
        float v0 = (lane < Ss) ? sw[lane] : -3.4e38f;
        float v1 = (lane + 32 < Ss) ? sw[lane + 32] : -3.4e38f;
        float m = fmaxf(v0, v1);
#pragma unroll
        for (int o = 16; o > 0; o >>= 1) m = fmaxf(m, __shfl_xor_sync(0xffffffffu, m, o));
        float e0 = (lane < Ss) ? expf(v0 - m) : 0.f;
        float e1 = (lane + 32 < Ss) ? expf(v1 - m) : 0.f;
        float sum = e0 + e1;
#pragma unroll
        for (int o = 16; o > 0; o >>= 1) sum += __shfl_xor_sync(0xffffffffu, sum, o);
        float inv = 1.0f / sum;
        if (lane < Ss) sw[lane] = e0 * inv;
        if (lane + 32 < Ss) sw[lane + 32] = e1 * inv;
    }
    __syncthreads();
    for (int d = tid; d < Hh; d += 256) {
        const float* vr = g_vals + (b * Hh + d) * Ss;
        float a = 0.f;
#pragma unroll
        for (int s = 0; s < Ss; s++) a = fmaf(sw[s], vr[s], a);
        g_attnT[l][K4B(d, b)] = a;
    }
    if (l == 0) {  // block-uniform branch: gather next-token embedding, reset argmax
        unsigned vtok = ~(unsigned)(g_amax[b]);
        for (int k = tid; k < Hh; k += 256)
            g_embT[K4B(k, b)] = embed[(size_t)vtok * Hh + k];
        __syncthreads();
        if (tid == 0) g_amax[b] = 0ull;
    }
}

// ---------------- gated hidden update: h = tanh([attn, h] @ hattW^T + hattb) ----------------
__global__ __launch_bounds__(128) void k_hatt(const longlong2* __restrict__ Wh,
                                              const float* __restrict__ hb) {
    int warp = (blockIdx.x * blockDim.x + threadIdx.x) >> 5;  // 0..127
    int b = threadIdx.x & 31;
    int d0 = warp * 4;
    const longlong2* at0 = (const longlong2*)g_attnT[0];
    const longlong2* at1 = (const longlong2*)g_attnT[1];
    const longlong2* h0 = (const longlong2*)g_hB[0];
    const longlong2* h1 = (const longlong2*)g_hB[1];
    ull a0[4] = {0ull, 0ull, 0ull, 0ull}, a1[4] = {0ull, 0ull, 0ull, 0ull};
    for (int k4 = 0; k4 < Hh / 4; k4++) {
        longlong2 av0 = at0[k4 * Bz + b], av1 = at1[k4 * Bz + b];
        longlong2 hv0 = h0[k4 * Bz + b], hv1 = h1[k4 * Bz + b];
#pragma unroll
        for (int r = 0; r < 4; r++) {
            int row = d0 + r;
            longlong2 wA = Wh[row * 256 + k4];         // attn half  (floats [0,512))
            longlong2 wH = Wh[row * 256 + 128 + k4];   // h half     (floats [512,1024))
            fma2(a0[r], (ull)wA.x, (ull)av0.x);
            fma2(a0[r], (ull)wA.y, (ull)av0.y);
            fma2(a0[r], (ull)wH.x, (ull)hv0.x);
            fma2(a0[r], (ull)wH.y, (ull)hv0.y);
            fma2(a1[r], (ull)wA.x, (ull)av1.x);
            fma2(a1[r], (ull)wA.y, (ull)av1.y);
            fma2(a1[r], (ull)wH.x, (ull)hv1.x);
            fma2(a1[r], (ull)wH.y, (ull)hv1.y);
        }
    }
#pragma unroll
    for (int r = 0; r < 4; r++) {
        int d = d0 + r;
        g_hA[0][K4B(d, b)] = tanhf(unpk_sum(a0[r]) + hb[d]);
        g_hA[1][K4B(d, b)] = tanhf(unpk_sum(a1[r]) + hb[d]);
    }
}

// ---------------- launch ----------------
extern "C" void kernel_launch(void* const* d_in, const int* in_sizes, int n_in,
                              void* d_out, int out_size) {
    (void)in_sizes; (void)n_in; (void)out_size;
    const float* img    = (const float*)d_in[0];
    const float* pooled = (const float*)d_in[1];
    const float* embed  = (const float*)d_in[2];
    const float* Wq     = (const float*)d_in[3];
    const float* bq     = (const float*)d_in[4];
    const float* Wk     = (const float*)d_in[5];
    const float* bk     = (const float*)d_in[6];
    const float* Wv     = (const float*)d_in[7];
    const float* bv     = (const float*)d_in[8];
    const float* Wih    = (const float*)d_in[9];
    const float* Whh    = (const float*)d_in[10];
    const float* bih    = (const float*)d_in[11];
    const float* bhh    = (const float*)d_in[12];
    const float* projW  = (const float*)d_in[13];
    const float* projb  = (const float*)d_in[14];
    const float* hattW  = (const float*)d_in[15];
    const float* hattb  = (const float*)d_in[16];
    const int*   sosp   = (const int*)d_in[17];
    float* res = (float*)d_out;

    k_init<<<128, 256>>>(pooled, embed, sosp);
    k_kv<<<Bz * Hh, 64>>>(img, Wk, bk, Wv, bv);

    // column t=0 from the <SOS> embedding (no argmax)
    k_proj<<<625, 128>>>(1, (const longlong2*)projW, projb, res, 0, 0);

    for (int t = 1; t < Tt; t++) {
        k_lstm<<<128, 128>>>(0, 1,
                             (const longlong2*)(Wih + 0 * 4 * Hh * Hh),
                             (const longlong2*)(Whh + 0 * 4 * Hh * Hh),
                             bih + 0 * 4 * Hh, bhh + 0 * 4 * Hh);
        k_lstm<<<128, 128>>>(1, 0,
                             (const longlong2*)(Wih + 1 * 4 * Hh * Hh),
                             (const longlong2*)(Whh + 1 * 4 * Hh * Hh),
                             bih + 1 * 4 * Hh, bhh + 1 * 4 * Hh);
        k_proj<<<625, 128>>>(0, (const longlong2*)projW, projb, res, t, 1);
        k_q<<<32, 128>>>((const longlong2*)Wq, bq);
        k_att<<<64, 256>>>(embed);
        k_hatt<<<32, 128>>>((const longlong2*)hattW, hattb);
    }
}

// round 7
// speedup vs baseline: 2.0857x; 2.0857x over previous
#include <cuda_runtime.h>
#include <cstdint>

#define Bz 32
#define Hh 512
#define Ll 2
#define Tt 20
#define Vv 10000
#define Ss 49

typedef unsigned long long ull;

// ---------------- device state (no allocations allowed) ----------------
__device__ __align__(16) float g_embT[Hh * Bz];          // k4b4 layout
__device__ __align__(16) float g_hA[Ll][Hh * Bz];        // gated h (LSTM input), k4b4
__device__ __align__(16) float g_hB[Ll][Hh * Bz];        // post-LSTM h, k4b4
__device__ __align__(16) float g_cT[Ll][Hh * Bz];        // plain [k*32+b]
__device__ __align__(16) float g_attnT[Ll][Hh * Bz];     // k4b4
__device__ float g_q[Ll][Hh][Bz];
__device__ float g_keysT[Bz * Ss * Hh];                  // [b][s][d]
__device__ float g_vals[Bz * Hh * Ss];                   // [b][d][s]
__device__ ull   g_amax[Bz];

// ---------------- helpers ----------------
__device__ __forceinline__ void fma2(ull& d, ull a, ull b) {
    asm("fma.rn.f32x2 %0, %1, %2, %0;" : "+l"(d) : "l"(a), "l"(b));
}
__device__ __forceinline__ float unpk_sum(ull v) {
    float lo, hi;
    asm("mov.b64 {%0,%1}, %2;" : "=f"(lo), "=f"(hi) : "l"(v));
    return lo + hi;
}
__device__ __forceinline__ int K4B(int k, int b) { return ((k >> 2) * Bz + b) * 4 + (k & 3); }
__device__ __forceinline__ float sigf(float x) { return 1.0f / (1.0f + expf(-x)); }
__device__ __forceinline__ unsigned fkey(float f) {
    unsigned u = __float_as_uint(f);
    return (u & 0x80000000u) ? ~u : (u | 0x80000000u);
}

// ---------------- init ----------------
__global__ void k_init(const float* __restrict__ pooled, const float* __restrict__ embed,
                       const int* __restrict__ sosp) {
    int i = blockIdx.x * blockDim.x + threadIdx.x;   // 32768 threads
    int sos = sosp[0];
    if (i < Ll * Hh * Bz) {
        int l = i / (Hh * Bz);
        int r = i % (Hh * Bz);
        int k = r >> 5, b = r & 31;
        float pv = pooled[b * Hh + k];
        g_hA[l][K4B(k, b)] = pv;
        g_cT[l][k * Bz + b] = pv;
    }
    if (i < Hh * Bz) {
        int k = i >> 5, b = i & 31;
        g_embT[K4B(k, b)] = embed[sos * Hh + k];
    }
    if (i < Bz) g_amax[i] = 0ull;
}

// ---------------- keys/values precompute (once) ----------------
__global__ void k_kv(const float* __restrict__ img, const float* __restrict__ Wk,
                     const float* __restrict__ bk, const float* __restrict__ Wv,
                     const float* __restrict__ bv) {
    int bd = blockIdx.x;               // b*512 + d
    int b = bd >> 9, d = bd & 511;
    __shared__ float ch[Ss];
    int tid = threadIdx.x;
    if (tid < Ss) ch[tid] = img[(b * Hh + d) * Ss + tid];
    __syncthreads();
    if (tid < Ss) {
        int s = tid;
        float ka = bk[s], va = bv[s];
        const float* wkr = Wk + s * Ss;
        const float* wvr = Wv + s * Ss;
#pragma unroll
        for (int s2 = 0; s2 < Ss; s2++) {
            float c = ch[s2];
            ka = fmaf(c, wkr[s2], ka);
            va = fmaf(c, wvr[s2], va);
        }
        g_keysT[(b * Ss + s) * Hh + d] = tanhf(ka);
        g_vals[(b * Hh + d) * Ss + s] = tanhf(va);
    }
}

// ---------------- LSTM layer: split-K=4, one block per gate row jj ----------------
__global__ __launch_bounds__(128) void k_lstm(
    int layer, int x_is_emb,
    const longlong2* __restrict__ Wih, const longlong2* __restrict__ Whh,
    const float* __restrict__ bih, const float* __restrict__ bhh) {
    int jj = blockIdx.x;                      // 0..511
    int w = threadIdx.x >> 5, b = threadIdx.x & 31;
    const longlong2* xT = x_is_emb ? (const longlong2*)g_embT : (const longlong2*)g_hB[0];
    const longlong2* hT = (const longlong2*)g_hA[layer];

    ull acc[4] = {0ull, 0ull, 0ull, 0ull};
    int k4b = w * 32;
#pragma unroll 2
    for (int i = 0; i < 32; i++) {
        int k4 = k4b + i;
        longlong2 xv = xT[k4 * Bz + b];
        longlong2 hv = hT[k4 * Bz + b];
#pragma unroll
        for (int g = 0; g < 4; g++) {
            int r = g * Hh + jj;
            longlong2 wi = Wih[r * (Hh / 4) + k4];
            longlong2 wh = Whh[r * (Hh / 4) + k4];
            fma2(acc[g], (ull)wi.x, (ull)xv.x);
            fma2(acc[g], (ull)wi.y, (ull)xv.y);
            fma2(acc[g], (ull)wh.x, (ull)hv.x);
            fma2(acc[g], (ull)wh.y, (ull)hv.y);
        }
    }
    __shared__ float red[4][4][32];
#pragma unroll
    for (int g = 0; g < 4; g++) red[w][g][b] = unpk_sum(acc[g]);
    __syncthreads();
    if (threadIdx.x < 32) {
        int bb = threadIdx.x;
        float gate[4];
#pragma unroll
        for (int g = 0; g < 4; g++)
            gate[g] = red[0][g][bb] + red[1][g][bb] + red[2][g][bb] + red[3][g][bb]
                    + bih[g * Hh + jj] + bhh[g * Hh + jj];
        float iv = sigf(gate[0]), fv = sigf(gate[1]);
        float gv = tanhf(gate[2]), ov = sigf(gate[3]);
        int ci = jj * Bz + bb;
        float c2 = fv * g_cT[layer][ci] + iv * gv;
        g_cT[layer][ci] = c2;
        g_hB[layer][K4B(jj, bb)] = ov * tanhf(c2);
    }
}

// ---------------- projection: 8 vocab rows per warp, logits -> res column + argmax ----------------
__global__ __launch_bounds__(128) void k_proj(
    int src_is_emb, const longlong2* __restrict__ W, const float* __restrict__ pb,
    float* __restrict__ res, int t, int do_amax) {
    __shared__ ull samax[Bz];
    int tid = threadIdx.x;
    if (tid < Bz) samax[tid] = 0ull;
    __syncthreads();
    const longlong2* xT = src_is_emb ? (const longlong2*)g_embT : (const longlong2*)g_hB[1];
    int warp = (blockIdx.x * blockDim.x + tid) >> 5;   // 0..1251
    int b = tid & 31;
    int v0 = warp * 8;
    int vr[8];
#pragma unroll
    for (int r = 0; r < 8; r++) vr[r] = (v0 + r < Vv) ? (v0 + r) : (Vv - 1);
    ull acc[8] = {0ull, 0ull, 0ull, 0ull, 0ull, 0ull, 0ull, 0ull};
#pragma unroll 2
    for (int k4 = 0; k4 < Hh / 4; k4++) {
        longlong2 xv = xT[k4 * Bz + b];
#pragma unroll
        for (int r = 0; r < 8; r++) {
            longlong2 wv = W[vr[r] * (Hh / 4) + k4];
            fma2(acc[r], (ull)wv.x, (ull)xv.x);
            fma2(acc[r], (ull)wv.y, (ull)xv.y);
        }
    }
    ull best = 0ull;
#pragma unroll
    for (int r = 0; r < 8; r++) {
        int v = v0 + r;
        if (v < Vv) {
            float lg = unpk_sum(acc[r]) + pb[v];
            res[b * (Vv * Tt) + v * Tt + t] = lg;
            ull pk = ((ull)fkey(lg) << 32) | (unsigned)(~(unsigned)v);
            if (pk > best) best = pk;
        }
    }
    if (do_amax) {
        atomicMax(&samax[b], best);
        __syncthreads();
        if (tid < Bz) atomicMax(&g_amax[tid], samax[tid]);
    }
}

// ---------------- q = tanh(h @ Wq^T + bq): split-K=4, block per 4 output dims ----------------
__global__ __launch_bounds__(128) void k_q(const longlong2* __restrict__ Wq,
                                           const float* __restrict__ bq) {
    int d0 = blockIdx.x * 4;                  // 128 blocks
    int w = threadIdx.x >> 5, b = threadIdx.x & 31;
    const longlong2* h0 = (const longlong2*)g_hB[0];
    const longlong2* h1 = (const longlong2*)g_hB[1];
    ull a0[4] = {0ull, 0ull, 0ull, 0ull}, a1[4] = {0ull, 0ull, 0ull, 0ull};
    int k4b = w * 32;
#pragma unroll 2
    for (int i = 0; i < 32; i++) {
        int k4 = k4b + i;
        longlong2 x0 = h0[k4 * Bz + b];
        longlong2 x1 = h1[k4 * Bz + b];
#pragma unroll
        for (int r = 0; r < 4; r++) {
            longlong2 wv = Wq[(d0 + r) * (Hh / 4) + k4];
            fma2(a0[r], (ull)wv.x, (ull)x0.x);
            fma2(a0[r], (ull)wv.y, (ull)x0.y);
            fma2(a1[r], (ull)wv.x, (ull)x1.x);
            fma2(a1[r], (ull)wv.y, (ull)x1.y);
        }
    }
    __shared__ float red[4][8][32];
#pragma unroll
    for (int r = 0; r < 4; r++) {
        red[w][r][b] = unpk_sum(a0[r]);
        red[w][r + 4][b] = unpk_sum(a1[r]);
    }
    __syncthreads();
    // 128 threads: r = tid>>5 (0..3), b = tid&31; each does both layers
    {
        int r = threadIdx.x >> 5, bb = threadIdx.x & 31;
        int d = d0 + r;
        float s0 = red[0][r][bb] + red[1][r][bb] + red[2][r][bb] + red[3][r][bb];
        float s1 = red[0][r + 4][bb] + red[1][r + 4][bb] + red[2][r + 4][bb] + red[3][r + 4][bb];
        float bv = bq[d];
        g_q[0][d][bb] = tanhf(s0 + bv);
        g_q[1][d][bb] = tanhf(s1 + bv);
    }
}

// ---------------- attention (scores/softmax/attn) + greedy-token embedding gather ----------------
__global__ __launch_bounds__(256) void k_att(const float* __restrict__ embed) {
    int l = blockIdx.x >> 5, b = blockIdx.x & 31;
    int tid = threadIdx.x;
    __shared__ float sq[Hh];
    __shared__ float sw[64];
    for (int d = tid; d < Hh; d += 256) sq[d] = g_q[l][d][b];
    __syncthreads();
    int w = tid >> 5, lane = tid & 31;
    for (int s = w; s < Ss; s += 8) {
        const float* kr = g_keysT + (b * Ss + s) * Hh;
        float acc = 0.f;
        for (int d = lane; d < Hh; d += 32) acc = fmaf(sq[d], kr[d], acc);
#pragma unroll
        for (int o = 16; o > 0; o >>= 1) acc += __shfl_down_sync(0xffffffffu, acc, o);
        if (lane == 0) sw[s] = acc * (1.0f / 7.0f);
    }
    __syncthreads();
    if (w == 0) {
        float v0 = (lane < Ss) ? sw[lane] : -3.4e38f;
        float v1 = (lane + 32 < Ss) ? sw[lane + 32] : -3.4e38f;
        float m = fmaxf(v0, v1);
#pragma unroll
        for (int o = 16; o > 0; o >>= 1) m = fmaxf(m, __shfl_xor_sync(0xffffffffu, m, o));
        float e0 = (lane < Ss) ? expf(v0 - m) : 0.f;
        float e1 = (lane + 32 < Ss) ? expf(v1 - m) : 0.f;
        float sum = e0 + e1;
#pragma unroll
        for (int o = 16; o > 0; o >>= 1) sum += __shfl_xor_sync(0xffffffffu, sum, o);
        float inv = 1.0f / sum;
        if (lane < Ss) sw[lane] = e0 * inv;
        if (lane + 32 < Ss) sw[lane + 32] = e1 * inv;
    }
    __syncthreads();
    for (int d = tid; d < Hh; d += 256) {
        const float* vr = g_vals + (b * Hh + d) * Ss;
        float a = 0.f;
#pragma unroll
        for (int s = 0; s < Ss; s++) a = fmaf(sw[s], vr[s], a);
        g_attnT[l][K4B(d, b)] = a;
    }
    if (l == 0) {  // block-uniform branch: gather next-token embedding, reset argmax
        unsigned vtok = ~(unsigned)(g_amax[b]);
        for (int k = tid; k < Hh; k += 256)
            g_embT[K4B(k, b)] = embed[(size_t)vtok * Hh + k];
        __syncthreads();
        if (tid == 0) g_amax[b] = 0ull;
    }
}

// ---------------- gated hidden update: split-K=4, block per 4 output dims ----------------
__global__ __launch_bounds__(128) void k_hatt(const longlong2* __restrict__ Wh,
                                              const float* __restrict__ hb) {
    int d0 = blockIdx.x * 4;                  // 128 blocks
    int w = threadIdx.x >> 5, b = threadIdx.x & 31;
    const longlong2* at0 = (const longlong2*)g_attnT[0];
    const longlong2* at1 = (const longlong2*)g_attnT[1];
    const longlong2* h0 = (const longlong2*)g_hB[0];
    const longlong2* h1 = (const longlong2*)g_hB[1];
    ull a0[4] = {0ull, 0ull, 0ull, 0ull}, a1[4] = {0ull, 0ull, 0ull, 0ull};
    int k4b = w * 32;
#pragma unroll 2
    for (int i = 0; i < 32; i++) {
        int k4 = k4b + i;
        longlong2 av0 = at0[k4 * Bz + b], av1 = at1[k4 * Bz + b];
        longlong2 hv0 = h0[k4 * Bz + b], hv1 = h1[k4 * Bz + b];
#pragma unroll
        for (int r = 0; r < 4; r++) {
            int row = d0 + r;
            longlong2 wA = Wh[row * 256 + k4];         // attn half  (floats [0,512))
            longlong2 wH = Wh[row * 256 + 128 + k4];   // h half     (floats [512,1024))
            fma2(a0[r], (ull)wA.x, (ull)av0.x);
            fma2(a0[r], (ull)wA.y, (ull)av0.y);
            fma2(a0[r], (ull)wH.x, (ull)hv0.x);
            fma2(a0[r], (ull)wH.y, (ull)hv0.y);
            fma2(a1[r], (ull)wA.x, (ull)av1.x);
            fma2(a1[r], (ull)wA.y, (ull)av1.y);
            fma2(a1[r], (ull)wH.x, (ull)hv1.x);
            fma2(a1[r], (ull)wH.y, (ull)hv1.y);
        }
    }
    __shared__ float red[4][8][32];
#pragma unroll
    for (int r = 0; r < 4; r++) {
        red[w][r][b] = unpk_sum(a0[r]);
        red[w][r + 4][b] = unpk_sum(a1[r]);
    }
    __syncthreads();
    {
        int r = threadIdx.x >> 5, bb = threadIdx.x & 31;
        int d = d0 + r;
        float s0 = red[0][r][bb] + red[1][r][bb] + red[2][r][bb] + red[3][r][bb];
        float s1 = red[0][r + 4][bb] + red[1][r + 4][bb] + red[2][r + 4][bb] + red[3][r + 4][bb];
        float bv = hb[d];
        g_hA[0][K4B(d, bb)] = tanhf(s0 + bv);
        g_hA[1][K4B(d, bb)] = tanhf(s1 + bv);
    }
}

// ---------------- launch ----------------
extern "C" void kernel_launch(void* const* d_in, const int* in_sizes, int n_in,
                              void* d_out, int out_size) {
    (void)in_sizes; (void)n_in; (void)out_size;
    const float* img    = (const float*)d_in[0];
    const float* pooled = (const float*)d_in[1];
    const float* embed  = (const float*)d_in[2];
    const float* Wq     = (const float*)d_in[3];
    const float* bq     = (const float*)d_in[4];
    const float* Wk     = (const float*)d_in[5];
    const float* bk     = (const float*)d_in[6];
    const float* Wv     = (const float*)d_in[7];
    const float* bv     = (const float*)d_in[8];
    const float* Wih    = (const float*)d_in[9];
    const float* Whh    = (const float*)d_in[10];
    const float* bih    = (const float*)d_in[11];
    const float* bhh    = (const float*)d_in[12];
    const float* projW  = (const float*)d_in[13];
    const float* projb  = (const float*)d_in[14];
    const float* hattW  = (const float*)d_in[15];
    const float* hattb  = (const float*)d_in[16];
    const int*   sosp   = (const int*)d_in[17];
    float* res = (float*)d_out;

    k_init<<<128, 256>>>(pooled, embed, sosp);
    k_kv<<<Bz * Hh, 64>>>(img, Wk, bk, Wv, bv);

    // column t=0 from the <SOS> embedding (no argmax)
    k_proj<<<313, 128>>>(1, (const longlong2*)projW, projb, res, 0, 0);

    for (int t = 1; t < Tt; t++) {
        k_lstm<<<512, 128>>>(0, 1,
                             (const longlong2*)(Wih + 0 * 4 * Hh * Hh),
                             (const longlong2*)(Whh + 0 * 4 * Hh * Hh),
                             bih + 0 * 4 * Hh, bhh + 0 * 4 * Hh);
        k_lstm<<<512, 128>>>(1, 0,
                             (const longlong2*)(Wih + 1 * 4 * Hh * Hh),
                             (const longlong2*)(Whh + 1 * 4 * Hh * Hh),
                             bih + 1 * 4 * Hh, bhh + 1 * 4 * Hh);
        k_proj<<<313, 128>>>(0, (const longlong2*)projW, projb, res, t, 1);
        k_q<<<128, 128>>>((const longlong2*)Wq, bq);
        k_att<<<64, 256>>>(embed);
        k_hatt<<<128, 128>>>((const longlong2*)hattW, hattb);
    }
}

// round 8
// speedup vs baseline: 2.9409x; 1.4100x over previous
#include <cuda_runtime.h>
#include <cstdint>

#define Bz 32
#define Hh 512
#define Ll 2
#define Tt 20
#define Vv 10000
#define Ss 49
#define GRID 148

typedef unsigned long long ull;

// ---------------- device state (no allocations allowed) ----------------
__device__ __align__(16) float g_embT[Hh * Bz];          // k4b4 layout
__device__ __align__(16) float g_hA[Ll][Hh * Bz];        // gated h (LSTM input), k4b4
__device__ __align__(16) float g_hB[Ll][Hh * Bz];        // post-LSTM h, k4b4
__device__ __align__(16) float g_cT[Ll][Hh * Bz];        // plain [k*32+b]
__device__ __align__(16) float g_attnT[Ll][Hh * Bz];     // k4b4
__device__ float g_q[Ll][Hh][Bz];
__device__ float g_keysT[Bz * Ss * Hh];                  // [b][s][d]
__device__ float g_vals[Bz * Hh * Ss];                   // [b][d][s]
__device__ ull   g_amax[Bz];
__device__ int   g_count;
__device__ int   g_gen;

// ---------------- helpers ----------------
__device__ __forceinline__ void fma2(ull& d, ull a, ull b) {
    asm("fma.rn.f32x2 %0, %1, %2, %0;" : "+l"(d) : "l"(a), "l"(b));
}
__device__ __forceinline__ float unpk_sum(ull v) {
    float lo, hi;
    asm("mov.b64 {%0,%1}, %2;" : "=f"(lo), "=f"(hi) : "l"(v));
    return lo + hi;
}
__device__ __forceinline__ int K4B(int k, int b) { return ((k >> 2) * Bz + b) * 4 + (k & 3); }
__device__ __forceinline__ float sigf(float x) { return 1.0f / (1.0f + expf(-x)); }
__device__ __forceinline__ unsigned fkey(float f) {
    unsigned u = __float_as_uint(f);
    return (u & 0x80000000u) ? ~u : (u | 0x80000000u);
}

// grid-wide barrier: monotonically increasing generation, arrive via atomicAdd,
// release/acquire on g_gen. All GRID blocks are co-resident (grid == 148 <= SM count,
// 1 block/SM), so spinning cannot deadlock.
__device__ __forceinline__ void gridbar(int gen) {
    __syncthreads();
    if (threadIdx.x == 0) {
        __threadfence();
        if (atomicAdd(&g_count, 1) == GRID - 1) {
            g_count = 0;
            __threadfence();
            asm volatile("st.release.gpu.b32 [%0], %1;" :: "l"(&g_gen), "r"(gen) : "memory");
        } else {
            int v;
            do {
                asm volatile("ld.acquire.gpu.b32 %0, [%1];" : "=r"(v) : "l"(&g_gen) : "memory");
            } while (v < gen);
        }
    }
    __syncthreads();
}

// ---------------- init (runs every launch; also resets the barrier) ----------------
__global__ void k_init(const float* __restrict__ pooled, const float* __restrict__ embed,
                       const int* __restrict__ sosp) {
    int i = blockIdx.x * blockDim.x + threadIdx.x;
    int sos = sosp[0];
    if (i == 0) { g_count = 0; g_gen = 0; }
    if (i < Ll * Hh * Bz) {
        int l = i / (Hh * Bz);
        int r = i % (Hh * Bz);
        int k = r >> 5, b = r & 31;
        float pv = pooled[b * Hh + k];
        g_hA[l][K4B(k, b)] = pv;
        g_cT[l][k * Bz + b] = pv;
    }
    if (i < Hh * Bz) {
        int k = i >> 5, b = i & 31;
        g_embT[K4B(k, b)] = embed[sos * Hh + k];
    }
    if (i < Bz) g_amax[i] = 0ull;
}

// ---------------- keys/values precompute (once) ----------------
__global__ void k_kv(const float* __restrict__ img, const float* __restrict__ Wk,
                     const float* __restrict__ bk, const float* __restrict__ Wv,
                     const float* __restrict__ bv) {
    int bd = blockIdx.x;               // b*512 + d
    int b = bd >> 9, d = bd & 511;
    __shared__ float ch[Ss];
    int tid = threadIdx.x;
    if (tid < Ss) ch[tid] = img[(b * Hh + d) * Ss + tid];
    __syncthreads();
    if (tid < Ss) {
        int s = tid;
        float ka = bk[s], va = bv[s];
        const float* wkr = Wk + s * Ss;
        const float* wvr = Wv + s * Ss;
#pragma unroll
        for (int s2 = 0; s2 < Ss; s2++) {
            float c = ch[s2];
            ka = fmaf(c, wkr[s2], ka);
            va = fmaf(c, wvr[s2], va);
        }
        g_keysT[(b * Ss + s) * Hh + d] = tanhf(ka);
        g_vals[(b * Hh + d) * Ss + s] = tanhf(va);
    }
}

// ================= persistent-kernel phases =================

// LSTM layer: blocks 0..127, 4 gate-rows per block, split-K=4 (16 warps).
__device__ __forceinline__ void phase_lstm(
    float* red, int layer, int x_is_emb,
    const longlong2* __restrict__ Wih, const longlong2* __restrict__ Whh,
    const float* __restrict__ bih, const float* __restrict__ bhh) {
    int blk = blockIdx.x;
    if (blk >= 128) return;
    int tid = threadIdx.x;
    int wid = tid >> 5, b = tid & 31;
    int rl = wid >> 2, split = wid & 3;
    int jj = blk * 4 + rl;
    const longlong2* xT = x_is_emb ? (const longlong2*)g_embT : (const longlong2*)g_hB[0];
    const longlong2* hT = (const longlong2*)g_hA[layer];

    ull acc[4] = {0ull, 0ull, 0ull, 0ull};
    int k4b = split * 32;
#pragma unroll 2
    for (int i = 0; i < 32; i++) {
        int k4 = k4b + i;
        longlong2 xv = xT[k4 * Bz + b];
        longlong2 hv = hT[k4 * Bz + b];
#pragma unroll
        for (int g = 0; g < 4; g++) {
            longlong2 wi = Wih[(g * Hh + jj) * (Hh / 4) + k4];
            longlong2 wh = Whh[(g * Hh + jj) * (Hh / 4) + k4];
            fma2(acc[g], (ull)wi.x, (ull)xv.x);
            fma2(acc[g], (ull)wi.y, (ull)xv.y);
            fma2(acc[g], (ull)wh.x, (ull)hv.x);
            fma2(acc[g], (ull)wh.y, (ull)hv.y);
        }
    }
#pragma unroll
    for (int g = 0; g < 4; g++)
        red[((rl * 4 + split) * 4 + g) * 32 + b] = unpk_sum(acc[g]);
    __syncthreads();
    if (tid < 128) {
        int r2 = tid >> 5, bb = tid & 31;
        int j2 = blk * 4 + r2;
        float gate[4];
#pragma unroll
        for (int g = 0; g < 4; g++) {
            float s = 0.f;
#pragma unroll
            for (int sp = 0; sp < 4; sp++) s += red[((r2 * 4 + sp) * 4 + g) * 32 + bb];
            gate[g] = s + bih[g * Hh + j2] + bhh[g * Hh + j2];
        }
        float iv = sigf(gate[0]), fv = sigf(gate[1]);
        float gv = tanhf(gate[2]), ov = sigf(gate[3]);
        int ci = j2 * Bz + bb;
        float c2 = fv * g_cT[layer][ci] + iv * gv;
        g_cT[layer][ci] = c2;
        g_hB[layer][K4B(j2, bb)] = ov * tanhf(c2);
    }
}

// projection (+ fused q): warp-tasks 0..1249 = 8 vocab rows each (1250*8 == 10000),
// warp-tasks 1250..1761 = one q output dim each (both layers, shared weight loads).
__device__ __forceinline__ void phase_proj(
    ull* samax, const longlong2* __restrict__ W, const float* __restrict__ pb,
    float* __restrict__ res, int t, int src_emb, int do_amax,
    int doq, const longlong2* __restrict__ Wq, const float* __restrict__ bq) {
    int tid = threadIdx.x;
    if (do_amax) { if (tid < Bz) samax[tid] = 0ull; __syncthreads(); }
    int wg = blockIdx.x * 16 + (tid >> 5);
    int b = tid & 31;
    const longlong2* xT = src_emb ? (const longlong2*)g_embT : (const longlong2*)g_hB[1];
    if (wg < 1250) {
        int v0 = wg * 8;
        ull acc[8] = {0ull, 0ull, 0ull, 0ull, 0ull, 0ull, 0ull, 0ull};
#pragma unroll 2
        for (int k4 = 0; k4 < Hh / 4; k4++) {
            longlong2 xv = xT[k4 * Bz + b];
#pragma unroll
            for (int r = 0; r < 8; r++) {
                longlong2 wv = W[(v0 + r) * (Hh / 4) + k4];
                fma2(acc[r], (ull)wv.x, (ull)xv.x);
                fma2(acc[r], (ull)wv.y, (ull)xv.y);
            }
        }
        ull best = 0ull;
#pragma unroll
        for (int r = 0; r < 8; r++) {
            int v = v0 + r;
            float lg = unpk_sum(acc[r]) + pb[v];
            res[b * (Vv * Tt) + v * Tt + t] = lg;
            ull pk = ((ull)fkey(lg) << 32) | (unsigned)(~(unsigned)v);
            if (pk > best) best = pk;
        }
        if (do_amax) atomicMax(&samax[b], best);
    } else if (doq && wg < 1250 + Hh) {
        int d = wg - 1250;
        const longlong2* h0 = (const longlong2*)g_hB[0];
        const longlong2* h1 = (const longlong2*)g_hB[1];
        ull a0 = 0ull, a1 = 0ull;
#pragma unroll 2
        for (int k4 = 0; k4 < Hh / 4; k4++) {
            longlong2 wv = Wq[d * (Hh / 4) + k4];
            longlong2 x0 = h0[k4 * Bz + b];
            longlong2 x1 = h1[k4 * Bz + b];
            fma2(a0, (ull)wv.x, (ull)x0.x);
            fma2(a0, (ull)wv.y, (ull)x0.y);
            fma2(a1, (ull)wv.x, (ull)x1.x);
            fma2(a1, (ull)wv.y, (ull)x1.y);
        }
        float bv = bq[d];
        g_q[0][d][b] = tanhf(unpk_sum(a0) + bv);
        g_q[1][d][b] = tanhf(unpk_sum(a1) + bv);
    }
    if (do_amax) { __syncthreads(); if (tid < Bz) atomicMax(&g_amax[tid], samax[tid]); }
}

// attention: blocks 0..63 = (l,b) tasks, 512 threads each; l==0 blocks also gather
// the greedy next-token embedding and reset the argmax slot.
__device__ __forceinline__ void phase_att(float* sq, float* sw, const float* __restrict__ embed) {
    int blk = blockIdx.x;
    if (blk >= 64) return;
    int l = blk >> 5, b = blk & 31;
    int tid = threadIdx.x;
    for (int d = tid; d < Hh; d += 512) sq[d] = g_q[l][d][b];
    __syncthreads();
    int w = tid >> 5, lane = tid & 31;
    for (int s = w; s < Ss; s += 16) {
        const float* kr = g_keysT + (b * Ss + s) * Hh;
        float acc = 0.f;
        for (int d = lane; d < Hh; d += 32) acc = fmaf(sq[d], kr[d], acc);
#pragma unroll
        for (int o = 16; o > 0; o >>= 1) acc += __shfl_down_sync(0xffffffffu, acc, o);
        if (lane == 0) sw[s] = acc * (1.0f / 7.0f);
    }
    __syncthreads();
    if (w == 0) {
        float v0 = (lane < Ss) ? sw[lane] : -3.4e38f;
        float v1 = (lane + 32 < Ss) ? sw[lane + 32] : -3.4e38f;
        float m = fmaxf(v0, v1);
#pragma unroll
        for (int o = 16; o > 0; o >>= 1) m = fmaxf(m, __shfl_xor_sync(0xffffffffu, m, o));
        float e0 = (lane < Ss) ? expf(v0 - m) : 0.f;
        float e1 = (lane + 32 < Ss) ? expf(v1 - m) : 0.f;
        float sum = e0 + e1;
#pragma unroll
        for (int o = 16; o > 0; o >>= 1) sum += __shfl_xor_sync(0xffffffffu, sum, o);
        float inv = 1.0f / sum;
        if (lane < Ss) sw[lane] = e0 * inv;
        if (lane + 32 < Ss) sw[lane + 32] = e1 * inv;
    }
    __syncthreads();
    for (int d = tid; d < Hh; d += 512) {
        const float* vr = g_vals + (b * Hh + d) * Ss;
        float a = 0.f;
#pragma unroll
        for (int s = 0; s < Ss; s++) a = fmaf(sw[s], vr[s], a);
        g_attnT[l][K4B(d, b)] = a;
    }
    if (l == 0) {  // block-uniform branch
        unsigned vtok = ~(unsigned)(g_amax[b]);
        for (int k = tid; k < Hh; k += 512)
            g_embT[K4B(k, b)] = embed[(size_t)vtok * Hh + k];
        __syncthreads();
        if (tid == 0) g_amax[b] = 0ull;
    }
}

// gated hidden update: blocks 0..127, 4 output dims per block, split-K=16 (16 warps).
__device__ __forceinline__ void phase_hatt(float* red, const longlong2* __restrict__ Wh,
                                           const float* __restrict__ hb) {
    int blk = blockIdx.x;
    if (blk >= 128) return;
    int tid = threadIdx.x;
    int wid = tid >> 5, b = tid & 31;
    int d0 = blk * 4;
    const longlong2* at0 = (const longlong2*)g_attnT[0];
    const longlong2* at1 = (const longlong2*)g_attnT[1];
    const longlong2* h0 = (const longlong2*)g_hB[0];
    const longlong2* h1 = (const longlong2*)g_hB[1];
    ull a0[4] = {0ull, 0ull, 0ull, 0ull}, a1[4] = {0ull, 0ull, 0ull, 0ull};
    int k4b = wid * 8;
#pragma unroll
    for (int i = 0; i < 8; i++) {
        int k4 = k4b + i;
        longlong2 av0 = at0[k4 * Bz + b], av1 = at1[k4 * Bz + b];
        longlong2 hv0 = h0[k4 * Bz + b], hv1 = h1[k4 * Bz + b];
#pragma unroll
        for (int r = 0; r < 4; r++) {
            int row = d0 + r;
            longlong2 wA = Wh[row * 256 + k4];
            longlong2 wH = Wh[row * 256 + 128 + k4];
            fma2(a0[r], (ull)wA.x, (ull)av0.x);
            fma2(a0[r], (ull)wA.y, (ull)av0.y);
            fma2(a0[r], (ull)wH.x, (ull)hv0.x);
            fma2(a0[r], (ull)wH.y, (ull)hv0.y);
            fma2(a1[r], (ull)wA.x, (ull)av1.x);
            fma2(a1[r], (ull)wA.y, (ull)av1.y);
            fma2(a1[r], (ull)wH.x, (ull)hv1.x);
            fma2(a1[r], (ull)wH.y, (ull)hv1.y);
        }
    }
#pragma unroll
    for (int r = 0; r < 4; r++) {
        red[(wid * 8 + r) * 32 + b] = unpk_sum(a0[r]);
        red[(wid * 8 + r + 4) * 32 + b] = unpk_sum(a1[r]);
    }
    __syncthreads();
    if (tid < 128) {
        int r = tid >> 5, bb = tid & 31;
        int d = d0 + r;
        float s0 = 0.f, s1 = 0.f;
#pragma unroll
        for (int sp = 0; sp < 16; sp++) {
            s0 += red[(sp * 8 + r) * 32 + bb];
            s1 += red[(sp * 8 + r + 4) * 32 + bb];
        }
        float bv = hb[d];
        g_hA[0][K4B(d, bb)] = tanhf(s0 + bv);
        g_hA[1][K4B(d, bb)] = tanhf(s1 + bv);
    }
}

// ---------------- the persistent time-loop kernel ----------------
__global__ __launch_bounds__(512, 1) void k_loop(
    const longlong2* __restrict__ Wih, const longlong2* __restrict__ Whh,
    const float* __restrict__ bih, const float* __restrict__ bhh,
    const longlong2* __restrict__ projW, const float* __restrict__ projb,
    const longlong2* __restrict__ Wq, const float* __restrict__ bq,
    const longlong2* __restrict__ hattW, const float* __restrict__ hattb,
    const float* __restrict__ embed, float* __restrict__ res) {
    __shared__ float sbuf[4096];
    __shared__ ull samax[Bz];
    int gen = 0;

    // t = 0 column from the <SOS> embedding (no argmax, no q)
    phase_proj(samax, projW, projb, res, 0, 1, 0, 0, Wq, bq);
    gridbar(++gen);

    for (int t = 1; t < Tt; t++) {
        phase_lstm(sbuf, 0, 1, Wih, Whh, bih, bhh);
        gridbar(++gen);
        phase_lstm(sbuf, 1, 0, Wih + 4 * Hh * (Hh / 4), Whh + 4 * Hh * (Hh / 4),
                   bih + 4 * Hh, bhh + 4 * Hh);
        gridbar(++gen);
        phase_proj(samax, projW, projb, res, t, 0, 1, 1, Wq, bq);
        gridbar(++gen);
        phase_att(sbuf, sbuf + Hh, embed);
        gridbar(++gen);
        phase_hatt(sbuf, hattW, hattb);
        gridbar(++gen);
    }
}

// ---------------- launch ----------------
extern "C" void kernel_launch(void* const* d_in, const int* in_sizes, int n_in,
                              void* d_out, int out_size) {
    (void)in_sizes; (void)n_in; (void)out_size;
    const float* img    = (const float*)d_in[0];
    const float* pooled = (const float*)d_in[1];
    const float* embed  = (const float*)d_in[2];
    const float* Wq     = (const float*)d_in[3];
    const float* bq     = (const float*)d_in[4];
    const float* Wk     = (const float*)d_in[5];
    const float* bk     = (const float*)d_in[6];
    const float* Wv     = (const float*)d_in[7];
    const float* bv     = (const float*)d_in[8];
    const float* Wih    = (const float*)d_in[9];
    const float* Whh    = (const float*)d_in[10];
    const float* bih    = (const float*)d_in[11];
    const float* bhh    = (const float*)d_in[12];
    const float* projW  = (const float*)d_in[13];
    const float* projb  = (const float*)d_in[14];
    const float* hattW  = (const float*)d_in[15];
    const float* hattb  = (const float*)d_in[16];
    const int*   sosp   = (const int*)d_in[17];
    float* res = (float*)d_out;

    k_init<<<128, 256>>>(pooled, embed, sosp);
    k_kv<<<Bz * Hh, 64>>>(img, Wk, bk, Wv, bv);
    k_loop<<<GRID, 512>>>((const longlong2*)Wih, (const longlong2*)Whh, bih, bhh,
                          (const longlong2*)projW, projb,
                          (const longlong2*)Wq, bq,
                          (const longlong2*)hattW, hattb,
                          embed, res);
}

// round 9
// speedup vs baseline: 3.2061x; 1.0902x over previous
#include <cuda_runtime.h>
#include <cstdint>

#define Bz 32
#define Hh 512
#define Ll 2
#define Tt 20
#define Vv 10000
#define Ss 49
#define GRID 148

typedef unsigned long long ull;

// ---------------- device state (no allocations allowed) ----------------
__device__ __align__(16) float g_embT[Hh * Bz];          // k4b4 layout
__device__ __align__(16) float g_hA[Ll][Hh * Bz];        // gated h (LSTM input), k4b4
__device__ __align__(16) float g_hB[Ll][Hh * Bz];        // post-LSTM h, k4b4
__device__ __align__(16) float g_cT[Ll][Hh * Bz];        // plain [k*32+b]
__device__ __align__(16) float g_attnT[Ll][Hh * Bz];     // k4b4
__device__ float g_q[Ll][Hh][Bz];
__device__ float g_keysT[Bz * Ss * Hh];                  // [b][s][d]
__device__ float g_vals[Bz * Hh * Ss];                   // [b][d][s]
__device__ ull   g_amax[Bz];
__device__ int   g_count;
__device__ int   g_gen;

// ---------------- helpers ----------------
__device__ __forceinline__ void fma2(ull& d, ull a, ull b) {
    asm("fma.rn.f32x2 %0, %1, %2, %0;" : "+l"(d) : "l"(a), "l"(b));
}
__device__ __forceinline__ float unpk_sum(ull v) {
    float lo, hi;
    asm("mov.b64 {%0,%1}, %2;" : "=f"(lo), "=f"(hi) : "l"(v));
    return lo + hi;
}
__device__ __forceinline__ int K4B(int k, int b) { return ((k >> 2) * Bz + b) * 4 + (k & 3); }
__device__ __forceinline__ float sigf(float x) { return 1.0f / (1.0f + expf(-x)); }
__device__ __forceinline__ unsigned fkey(float f) {
    unsigned u = __float_as_uint(f);
    return (u & 0x80000000u) ? ~u : (u | 0x80000000u);
}

// grid-wide barrier, re-entrant across launches via base-relative generations.
__device__ __forceinline__ void gridbar(int gen) {
    __syncthreads();
    if (threadIdx.x == 0) {
        __threadfence();
        if (atomicAdd(&g_count, 1) == GRID - 1) {
            g_count = 0;
            __threadfence();
            asm volatile("st.release.gpu.b32 [%0], %1;" :: "l"(&g_gen), "r"(gen) : "memory");
        } else {
            int v;
            do {
                asm volatile("ld.acquire.gpu.b32 %0, [%1];" : "=r"(v) : "l"(&g_gen) : "memory");
            } while (v < gen);
        }
    }
    __syncthreads();
}

// ---------------- keys/values precompute (separate kernel, once per launch) ----------------
__global__ void k_kv(const float* __restrict__ img, const float* __restrict__ Wk,
                     const float* __restrict__ bk, const float* __restrict__ Wv,
                     const float* __restrict__ bv) {
    int bd = blockIdx.x;               // b*512 + d
    int b = bd >> 9, d = bd & 511;
    __shared__ float ch[Ss];
    int tid = threadIdx.x;
    if (tid < Ss) ch[tid] = img[(b * Hh + d) * Ss + tid];
    __syncthreads();
    if (tid < Ss) {
        int s = tid;
        float ka = bk[s], va = bv[s];
        const float* wkr = Wk + s * Ss;
        const float* wvr = Wv + s * Ss;
#pragma unroll
        for (int s2 = 0; s2 < Ss; s2++) {
            float c = ch[s2];
            ka = fmaf(c, wkr[s2], ka);
            va = fmaf(c, wvr[s2], va);
        }
        g_keysT[(b * Ss + s) * Hh + d] = tanhf(ka);
        g_vals[(b * Hh + d) * Ss + s] = tanhf(va);
    }
}

// ================= persistent-kernel phases =================

__device__ __forceinline__ void stage2(float4* sm0, const float4* src0,
                                       float4* sm1, const float4* src1) {
    for (int i = threadIdx.x; i < 4096; i += 512) { sm0[i] = src0[i]; sm1[i] = src1[i]; }
    __syncthreads();
}

// LSTM layer: blocks 0..127, 4 gate-rows per block, split-K=4 (16 warps).
// Activations staged in smem; only weights hit L1 (64KB/block slice -> resident).
__device__ __forceinline__ void phase_lstm(
    float* red, float4* sm0, float4* sm1, const float* xsrc, int layer,
    const longlong2* __restrict__ Wih, const longlong2* __restrict__ Whh,
    const float* __restrict__ bih, const float* __restrict__ bhh) {
    int blk = blockIdx.x;
    if (blk >= 128) return;
    stage2(sm0, (const float4*)xsrc, sm1, (const float4*)g_hA[layer]);
    const longlong2* xT = (const longlong2*)sm0;
    const longlong2* hT = (const longlong2*)sm1;
    int tid = threadIdx.x;
    int wid = tid >> 5, b = tid & 31;
    int rl = wid >> 2, split = wid & 3;
    int jj = blk * 4 + rl;

    ull acc[4] = {0ull, 0ull, 0ull, 0ull};
    int k4b = split * 32;
#pragma unroll 2
    for (int i = 0; i < 32; i++) {
        int k4 = k4b + i;
        longlong2 xv = xT[k4 * Bz + b];
        longlong2 hv = hT[k4 * Bz + b];
#pragma unroll
        for (int g = 0; g < 4; g++) {
            longlong2 wi = Wih[(g * Hh + jj) * (Hh / 4) + k4];
            longlong2 wh = Whh[(g * Hh + jj) * (Hh / 4) + k4];
            fma2(acc[g], (ull)wi.x, (ull)xv.x);
            fma2(acc[g], (ull)wi.y, (ull)xv.y);
            fma2(acc[g], (ull)wh.x, (ull)hv.x);
            fma2(acc[g], (ull)wh.y, (ull)hv.y);
        }
    }
#pragma unroll
    for (int g = 0; g < 4; g++)
        red[((rl * 4 + split) * 4 + g) * 32 + b] = unpk_sum(acc[g]);
    __syncthreads();
    if (tid < 128) {
        int r2 = tid >> 5, bb = tid & 31;
        int j2 = blk * 4 + r2;
        float gate[4];
#pragma unroll
        for (int g = 0; g < 4; g++) {
            float s = 0.f;
#pragma unroll
            for (int sp = 0; sp < 4; sp++) s += red[((r2 * 4 + sp) * 4 + g) * 32 + bb];
            gate[g] = s + bih[g * Hh + j2] + bhh[g * Hh + j2];
        }
        float iv = sigf(gate[0]), fv = sigf(gate[1]);
        float gv = tanhf(gate[2]), ov = sigf(gate[3]);
        int ci = j2 * Bz + bb;
        float c2 = fv * g_cT[layer][ci] + iv * gv;
        g_cT[layer][ci] = c2;
        g_hB[layer][K4B(j2, bb)] = ov * tanhf(c2);
    }
}

// projection (+ fused q). Interleaved tasks: task = wid*148 + blk.
// tasks 0..1249: 8 vocab rows each (exactly 10000). tasks 1250..1761: one q dim (both layers).
// sm0 <- proj source activations (hB[1] or embT), sm1 <- hB[0] (q second operand).
__device__ __forceinline__ void phase_proj(
    ull* samax, float4* sm0, float4* sm1,
    const longlong2* __restrict__ W, const float* __restrict__ pb,
    float* __restrict__ res, int t, int src_emb, int do_amax,
    int doq, const longlong2* __restrict__ Wq, const float* __restrict__ bq) {
    int tid = threadIdx.x;
    if (do_amax) { if (tid < Bz) samax[tid] = 0ull; }
    stage2(sm0, src_emb ? (const float4*)g_embT : (const float4*)g_hB[1],
           sm1, (const float4*)g_hB[0]);
    int task = (tid >> 5) * GRID + blockIdx.x;
    int b = tid & 31;
    const longlong2* xT = (const longlong2*)sm0;
    if (task < 1250) {
        int v0 = task * 8;
        ull acc[8] = {0ull, 0ull, 0ull, 0ull, 0ull, 0ull, 0ull, 0ull};
#pragma unroll 2
        for (int k4 = 0; k4 < Hh / 4; k4++) {
            longlong2 xv = xT[k4 * Bz + b];
#pragma unroll
            for (int r = 0; r < 8; r++) {
                longlong2 wv = W[(v0 + r) * (Hh / 4) + k4];
                fma2(acc[r], (ull)wv.x, (ull)xv.x);
                fma2(acc[r], (ull)wv.y, (ull)xv.y);
            }
        }
        ull best = 0ull;
#pragma unroll
        for (int r = 0; r < 8; r++) {
            int v = v0 + r;
            float lg = unpk_sum(acc[r]) + pb[v];
            res[b * (Vv * Tt) + v * Tt + t] = lg;
            ull pk = ((ull)fkey(lg) << 32) | (unsigned)(~(unsigned)v);
            if (pk > best) best = pk;
        }
        if (do_amax) atomicMax(&samax[b], best);
    } else if (doq && task < 1250 + Hh) {
        int d = task - 1250;
        const longlong2* h0 = (const longlong2*)sm1;
        const longlong2* h1 = (const longlong2*)sm0;
        ull a0 = 0ull, a1 = 0ull;
#pragma unroll 2
        for (int k4 = 0; k4 < Hh / 4; k4++) {
            longlong2 wv = Wq[d * (Hh / 4) + k4];
            longlong2 x0 = h0[k4 * Bz + b];
            longlong2 x1 = h1[k4 * Bz + b];
            fma2(a0, (ull)wv.x, (ull)x0.x);
            fma2(a0, (ull)wv.y, (ull)x0.y);
            fma2(a1, (ull)wv.x, (ull)x1.x);
            fma2(a1, (ull)wv.y, (ull)x1.y);
        }
        float bv = bq[d];
        g_q[0][d][b] = tanhf(unpk_sum(a0) + bv);
        g_q[1][d][b] = tanhf(unpk_sum(a1) + bv);
    }
    if (do_amax) { __syncthreads(); if (tid < Bz) atomicMax(&g_amax[tid], samax[tid]); }
}

// attention: blocks 0..63 = (l,b); l==0 blocks also gather next-token embedding.
__device__ __forceinline__ void phase_att(float* sq, float* sw, const float* __restrict__ embed) {
    int blk = blockIdx.x;
    if (blk >= 64) return;
    int l = blk >> 5, b = blk & 31;
    int tid = threadIdx.x;
    for (int d = tid; d < Hh; d += 512) sq[d] = g_q[l][d][b];
    __syncthreads();
    int w = tid >> 5, lane = tid & 31;
    for (int s = w; s < Ss; s += 16) {
        const float* kr = g_keysT + (b * Ss + s) * Hh;
        float acc = 0.f;
        for (int d = lane; d < Hh; d += 32) acc = fmaf(sq[d], kr[d], acc);
#pragma unroll
        for (int o = 16; o > 0; o >>= 1) acc += __shfl_down_sync(0xffffffffu, acc, o);
        if (lane == 0) sw[s] = acc * (1.0f / 7.0f);
    }
    __syncthreads();
    if (w == 0) {
        float v0 = (lane < Ss) ? sw[lane] : -3.4e38f;
        float v1 = (lane + 32 < Ss) ? sw[lane + 32] : -3.4e38f;
        float m = fmaxf(v0, v1);
#pragma unroll
        for (int o = 16; o > 0; o >>= 1) m = fmaxf(m, __shfl_xor_sync(0xffffffffu, m, o));
        float e0 = (lane < Ss) ? expf(v0 - m) : 0.f;
        float e1 = (lane + 32 < Ss) ? expf(v1 - m) : 0.f;
        float sum = e0 + e1;
#pragma unroll
        for (int o = 16; o > 0; o >>= 1) sum += __shfl_xor_sync(0xffffffffu, sum, o);
        float inv = 1.0f / sum;
        if (lane < Ss) sw[lane] = e0 * inv;
        if (lane + 32 < Ss) sw[lane + 32] = e1 * inv;
    }
    __syncthreads();
    for (int d = tid; d < Hh; d += 512) {
        const float* vr = g_vals + (b * Hh + d) * Ss;
        float a = 0.f;
#pragma unroll
        for (int s = 0; s < Ss; s++) a = fmaf(sw[s], vr[s], a);
        g_attnT[l][K4B(d, b)] = a;
    }
    if (l == 0) {
        unsigned vtok = ~(unsigned)(g_amax[b]);
        for (int k = tid; k < Hh; k += 512)
            g_embT[K4B(k, b)] = embed[(size_t)vtok * Hh + k];
        __syncthreads();
        if (tid == 0) g_amax[b] = 0ull;
    }
}

// gated hidden update: blocks 0..127, 4 output dims per block, split-K=16.
__device__ __forceinline__ void phase_hatt(float* red, const longlong2* __restrict__ Wh,
                                           const float* __restrict__ hb) {
    int blk = blockIdx.x;
    if (blk >= 128) return;
    int tid = threadIdx.x;
    int wid = tid >> 5, b = tid & 31;
    int d0 = blk * 4;
    const longlong2* at0 = (const longlong2*)g_attnT[0];
    const longlong2* at1 = (const longlong2*)g_attnT[1];
    const longlong2* h0 = (const longlong2*)g_hB[0];
    const longlong2* h1 = (const longlong2*)g_hB[1];
    ull a0[4] = {0ull, 0ull, 0ull, 0ull}, a1[4] = {0ull, 0ull, 0ull, 0ull};
    int k4b = wid * 8;
#pragma unroll
    for (int i = 0; i < 8; i++) {
        int k4 = k4b + i;
        longlong2 av0 = at0[k4 * Bz + b], av1 = at1[k4 * Bz + b];
        longlong2 hv0 = h0[k4 * Bz + b], hv1 = h1[k4 * Bz + b];
#pragma unroll
        for (int r = 0; r < 4; r++) {
            int row = d0 + r;
            longlong2 wA = Wh[row * 256 + k4];
            longlong2 wH = Wh[row * 256 + 128 + k4];
            fma2(a0[r], (ull)wA.x, (ull)av0.x);
            fma2(a0[r], (ull)wA.y, (ull)av0.y);
            fma2(a0[r], (ull)wH.x, (ull)hv0.x);
            fma2(a0[r], (ull)wH.y, (ull)hv0.y);
            fma2(a1[r], (ull)wA.x, (ull)av1.x);
            fma2(a1[r], (ull)wA.y, (ull)av1.y);
            fma2(a1[r], (ull)wH.x, (ull)hv1.x);
            fma2(a1[r], (ull)wH.y, (ull)hv1.y);
        }
    }
#pragma unroll
    for (int r = 0; r < 4; r++) {
        red[(wid * 8 + r) * 32 + b] = unpk_sum(a0[r]);
        red[(wid * 8 + r + 4) * 32 + b] = unpk_sum(a1[r]);
    }
    __syncthreads();
    if (tid < 128) {
        int r = tid >> 5, bb = tid & 31;
        int d = d0 + r;
        float s0 = 0.f, s1 = 0.f;
#pragma unroll
        for (int sp = 0; sp < 16; sp++) {
            s0 += red[(sp * 8 + r) * 32 + bb];
            s1 += red[(sp * 8 + r + 4) * 32 + bb];
        }
        float bv = hb[d];
        g_hA[0][K4B(d, bb)] = tanhf(s0 + bv);
        g_hA[1][K4B(d, bb)] = tanhf(s1 + bv);
    }
}

// ---------------- the persistent time-loop kernel (init folded in) ----------------
__global__ __launch_bounds__(512, 1) void k_loop(
    const float* __restrict__ pooled, const float* __restrict__ embed,
    const int* __restrict__ sosp,
    const longlong2* __restrict__ Wih, const longlong2* __restrict__ Whh,
    const float* __restrict__ bih, const float* __restrict__ bhh,
    const longlong2* __restrict__ projW, const float* __restrict__ projb,
    const longlong2* __restrict__ Wq, const float* __restrict__ bq,
    const longlong2* __restrict__ hattW, const float* __restrict__ hattb,
    float* __restrict__ res) {
    extern __shared__ float dyn[];
    float4* sm0 = (float4*)dyn;            // 64KB
    float4* sm1 = (float4*)(dyn + 16384);  // 64KB
    __shared__ float red[16 * 8 * 32];     // 16KB (lstm uses first 8KB)
    __shared__ float sq[Hh];
    __shared__ float sw[64];
    __shared__ ull samax[Bz];
    __shared__ int s_base;

    // base generation (re-entrant barrier across launches)
    if (threadIdx.x == 0) s_base = *(volatile int*)&g_gen;
    __syncthreads();
    int gen = s_base;

    // ---- init phase ----
    {
        int i = blockIdx.x * 512 + threadIdx.x;      // 75776 threads
        int sos = sosp[0];
        if (i < Ll * Hh * Bz) {
            int l = i / (Hh * Bz);
            int r = i % (Hh * Bz);
            int k = r >> 5, b = r & 31;
            float pv = pooled[b * Hh + k];
            g_hA[l][K4B(k, b)] = pv;
            g_cT[l][k * Bz + b] = pv;
        }
        if (i < Hh * Bz) {
            int k = i >> 5, b = i & 31;
            g_embT[K4B(k, b)] = embed[sos * Hh + k];
        }
        if (i < Bz) g_amax[i] = 0ull;
    }
    gridbar(++gen);

    // t = 0 column from the <SOS> embedding (no argmax, no q)
    phase_proj(samax, sm0, sm1, projW, projb, res, 0, 1, 0, 0, Wq, bq);
    gridbar(++gen);

    for (int t = 1; t < Tt; t++) {
        phase_lstm(red, sm0, sm1, g_embT, 0, Wih, Whh, bih, bhh);
        gridbar(++gen);
        phase_lstm(red, sm0, sm1, g_hB[0], 1, Wih + 4 * Hh * (Hh / 4), Whh + 4 * Hh * (Hh / 4),
                   bih + 4 * Hh, bhh + 4 * Hh);
        gridbar(++gen);
        phase_proj(samax, sm0, sm1, projW, projb, res, t, 0, 1, 1, Wq, bq);
        gridbar(++gen);
        phase_att(sq, sw, embed);
        gridbar(++gen);
        phase_hatt(red, hattW, hattb);
        gridbar(++gen);
    }
}

// ---------------- launch ----------------
extern "C" void kernel_launch(void* const* d_in, const int* in_sizes, int n_in,
                              void* d_out, int out_size) {
    (void)in_sizes; (void)n_in; (void)out_size;
    const float* img    = (const float*)d_in[0];
    const float* pooled = (const float*)d_in[1];
    const float* embed  = (const float*)d_in[2];
    const float* Wq     = (const float*)d_in[3];
    const float* bq     = (const float*)d_in[4];
    const float* Wk     = (const float*)d_in[5];
    const float* bk     = (const float*)d_in[6];
    const float* Wv     = (const float*)d_in[7];
    const float* bv     = (const float*)d_in[8];
    const float* Wih    = (const float*)d_in[9];
    const float* Whh    = (const float*)d_in[10];
    const float* bih    = (const float*)d_in[11];
    const float* bhh    = (const float*)d_in[12];
    const float* projW  = (const float*)d_in[13];
    const float* projb  = (const float*)d_in[14];
    const float* hattW  = (const float*)d_in[15];
    const float* hattb  = (const float*)d_in[16];
    const int*   sosp   = (const int*)d_in[17];
    float* res = (float*)d_out;

    cudaFuncSetAttribute(k_loop, cudaFuncAttributeMaxDynamicSharedMemorySize, 131072);
    k_kv<<<Bz * Hh, 64>>>(img, Wk, bk, Wv, bv);
    k_loop<<<GRID, 512, 131072>>>(pooled, embed, sosp,
                                  (const longlong2*)Wih, (const longlong2*)Whh, bih, bhh,
                                  (const longlong2*)projW, projb,
                                  (const longlong2*)Wq, bq,
                                  (const longlong2*)hattW, hattb,
                                  res);
}